// round 6
// baseline (speedup 1.0000x reference)
#include <cuda_runtime.h>
#include <cuda_fp16.h>
#include <cstdint>
#include <cstddef>

// ---------------------------------------------------------------------------
// W4A16 grouped-quant GEMM:  out[M,N] = x[M,K] @ dequant(W4)[N,K]^T
//   M = 8192, N = 11008, K = 4096, group = 128
//   weight_packed: int32[N, K/2]: one byte per int32, two int4 nibbles
//     even k -> low nibble, odd k -> high nibble; w = (nib-8)*scale[n][k/128]
// Inputs may arrive as fp16 OR fp32 (harness dtype support ambiguity): a sniff
// kernel detects, a convert pass materializes fp16 scratch, the HMMA GEMM runs
// on fp16, and the epilogue writes fp16 or fp32 (with fp16 rounding emulated).
// ---------------------------------------------------------------------------

namespace {
constexpr int Mdim = 8192;
constexpr int Ndim = 11008;
constexpr int Kdim = 4096;
constexpr int KPACK = Kdim / 2;
constexpr int NGROUPS = 32;
constexpr int BM = 128, BN = 128, BK = 64;
constexpr int LDS = BK + 8;
constexpr int THREADS = 256;
constexpr int BUF_HALFS = BM * LDS;
constexpr int SMEM_BYTES = 2 * 2 * BUF_HALFS * 2;          // 73728 B
constexpr long long XN = (long long)Mdim * Kdim;            // 33,554,432
constexpr long long WN = (long long)Ndim * KPACK;           // 22,544,384
constexpr long long SN = (long long)Ndim * NGROUPS;         //    352,256
}

__device__ int    g_is32;                      // 1 => inputs are fp32
__device__ __half g_xh[(size_t)XN];            // fp16 activations scratch
__device__ __half g_sh[(size_t)SN];            // fp16 scales scratch

// ------------------------------ pre-pass ----------------------------------
__global__ void sniff_kernel(const void* x) {
    const __half* h = (const __half*)x;
    int bad = 0;
    for (int i = threadIdx.x; i < 4096; i += 32) {
        float v = __half2float(h[i]);
        if (!isfinite(v) || fabsf(v) > 64.0f) bad++;
    }
    #pragma unroll
    for (int o = 16; o; o >>= 1) bad += __shfl_xor_sync(0xffffffffu, bad, o);
    if (threadIdx.x == 0) g_is32 = (bad > 8) ? 1 : 0;
}

__global__ void cvt_x_kernel(const void* src) {
    long long i = (long long)blockIdx.x * blockDim.x + threadIdx.x;
    if (i >= XN) return;
    g_xh[i] = g_is32 ? __float2half_rn(((const float*)src)[i])
                     : ((const __half*)src)[i];
}

__global__ void cvt_s_kernel(const void* src) {
    long long i = (long long)blockIdx.x * blockDim.x + threadIdx.x;
    if (i >= SN) return;
    g_sh[i] = g_is32 ? __float2half_rn(((const float*)src)[i])
                     : ((const __half*)src)[i];
}

// ------------------------------ GEMM core ----------------------------------
__device__ __forceinline__ void ldsm4(uint32_t* r, uint32_t addr) {
    asm volatile("ldmatrix.sync.aligned.m8n8.x4.shared.b16 {%0,%1,%2,%3}, [%4];\n"
                 : "=r"(r[0]), "=r"(r[1]), "=r"(r[2]), "=r"(r[3])
                 : "r"(addr) : "memory");
}

__device__ __forceinline__ void mma16816(float* c, const uint32_t* a,
                                         uint32_t b0, uint32_t b1) {
    asm volatile("mma.sync.aligned.m16n8k16.row.col.f32.f16.f16.f32 "
                 "{%0,%1,%2,%3}, {%4,%5,%6,%7}, {%8,%9}, {%0,%1,%2,%3};\n"
                 : "+f"(c[0]), "+f"(c[1]), "+f"(c[2]), "+f"(c[3])
                 : "r"(a[0]), "r"(a[1]), "r"(a[2]), "r"(a[3]), "r"(b0), "r"(b1));
}

__device__ __forceinline__ void cpasync16(uint32_t dst, const void* src) {
    asm volatile("cp.async.cg.shared.global [%0], [%1], 16;\n"
                 :: "r"(dst), "l"(src) : "memory");
}

// One packed byte -> half2 {(lo-8)*s, (hi-8)*s}, bit-exact fp16 like reference.
__device__ __forceinline__ uint32_t dq2(uint32_t byte, __half2 s2) {
    uint32_t p = 0x64006400u | (byte & 0x0Fu) | ((byte & 0xF0u) << 12);
    __half2 h = *reinterpret_cast<__half2*>(&p);                 // {1024+lo,1024+hi}
    h = __hsub2(h, __half2half2(__ushort_as_half((unsigned short)0x6408))); // -1032
    h = __hmul2(h, s2);
    return *reinterpret_cast<uint32_t*>(&h);
}

__global__ void __launch_bounds__(THREADS, 2)
w4a16_gemm(const int* __restrict__ WP, void* __restrict__ Ov)
{
    const __half* __restrict__ X = g_xh;
    const __half* __restrict__ S = g_sh;

    constexpr int NPN = Ndim / BN;   // 86
    constexpr int GM = 8;
    const int pid = blockIdx.x;
    const int nig = GM * NPN;
    const int first_m = (pid / nig) * GM;
    const int local = pid % nig;
    const int pid_m = first_m + (local % GM);
    const int pid_n = local / GM;
    const int m0 = pid_m * BM;
    const int n0 = pid_n * BN;

    const int tid  = threadIdx.x;
    const int lane = tid & 31;
    const int warp = tid >> 5;
    const int wm = warp >> 2;
    const int wn = warp & 3;

    extern __shared__ __half smem[];
    __half* As = smem;                       // [2][BM][LDS]
    __half* Bs = smem + 2 * BUF_HALFS;       // [2][BN][LDS]

    const int ldrow = tid >> 3;              // 0..31
    const int ldc   = tid & 7;               // 0..7

    const __half* aSrcBase = X  + (size_t)(m0 + ldrow) * Kdim  + ldc * 8;
    const int*    bSrcBase = WP + (size_t)(n0 + ldrow) * KPACK + ldc * 4;
    const __half* sSrcBase = S  + (size_t)(n0 + ldrow) * NGROUPS;

    const uint32_t aDst0 = (uint32_t)__cvta_generic_to_shared(As)
                         + (uint32_t)((ldrow * LDS + ldc * 8) * 2);
    const uint32_t bufBytes = BUF_HALFS * 2;

    float c[4][4][4];
    #pragma unroll
    for (int i = 0; i < 4; i++)
        #pragma unroll
        for (int j = 0; j < 4; j++)
            #pragma unroll
            for (int q = 0; q < 4; q++) c[i][j][q] = 0.f;

    int4   breg[4];
    __half bscl[4];

    // ---------------- prologue: stage tile 0 into buffer 0 ----------------
    {
        #pragma unroll
        for (int i = 0; i < 4; i++)
            cpasync16(aDst0 + (uint32_t)(i * 32 * LDS * 2),
                      aSrcBase + (size_t)i * 32 * Kdim);
        asm volatile("cp.async.commit_group;\n" ::: "memory");
        #pragma unroll
        for (int i = 0; i < 4; i++) {
            breg[i] = *reinterpret_cast<const int4*>(bSrcBase + (size_t)i * 32 * KPACK);
            bscl[i] = sSrcBase[(size_t)i * 32 * NGROUPS];
        }
        __half* bd = Bs + ldrow * LDS + ldc * 8;
        #pragma unroll
        for (int i = 0; i < 4; i++) {
            __half2 s2 = __half2half2(bscl[i]);
            uint32_t v[4];
            v[0] = dq2((uint32_t)breg[i].x, s2);
            v[1] = dq2((uint32_t)breg[i].y, s2);
            v[2] = dq2((uint32_t)breg[i].z, s2);
            v[3] = dq2((uint32_t)breg[i].w, s2);
            *reinterpret_cast<uint4*>(bd + (size_t)i * 32 * LDS) =
                *reinterpret_cast<uint4*>(v);
        }
        asm volatile("cp.async.wait_group 0;\n" ::: "memory");
        __syncthreads();
    }

    constexpr int NSTEP = Kdim / BK;  // 64
    #pragma unroll 1
    for (int s = 0; s < NSTEP; s++) {
        const int buf  = s & 1;
        const int nbuf = buf ^ 1;
        const int knext = (s + 1) * BK;

        if (s + 1 < NSTEP) {
            const uint32_t ad = aDst0 + (uint32_t)nbuf * bufBytes;
            const __half* asrc = aSrcBase + knext;
            #pragma unroll
            for (int i = 0; i < 4; i++)
                cpasync16(ad + (uint32_t)(i * 32 * LDS * 2),
                          asrc + (size_t)i * 32 * Kdim);
            asm volatile("cp.async.commit_group;\n" ::: "memory");
            const int* bsrc = bSrcBase + (knext >> 1);
            const int  g    = knext >> 7;
            #pragma unroll
            for (int i = 0; i < 4; i++) {
                breg[i] = *reinterpret_cast<const int4*>(bsrc + (size_t)i * 32 * KPACK);
                bscl[i] = sSrcBase[(size_t)i * 32 * NGROUPS + g];
            }
        }

        // ------------------------- compute on `buf` -------------------------
        {
            const uint32_t Ab = (uint32_t)__cvta_generic_to_shared(As) + (uint32_t)buf * bufBytes;
            const uint32_t Bb = (uint32_t)__cvta_generic_to_shared(Bs) + (uint32_t)buf * bufBytes;
            const int l15   = lane & 15;
            const int lk    = (lane >> 4) << 3;
            const int arowp = wm * 64 + l15;
            const int brows = wn * 32 + ((lane >> 4) << 3) + (lane & 7);
            const int bk8   = lane & 8;
            #pragma unroll
            for (int kb = 0; kb < 4; kb++) {
                uint32_t a[4][4];
                uint32_t b[2][4];
                #pragma unroll
                for (int mi = 0; mi < 4; mi++)
                    ldsm4(a[mi], Ab + (uint32_t)(((arowp + mi * 16) * LDS + kb * 16 + lk) * 2));
                #pragma unroll
                for (int p = 0; p < 2; p++)
                    ldsm4(b[p], Bb + (uint32_t)(((brows + p * 16) * LDS + kb * 16 + bk8) * 2));
                #pragma unroll
                for (int mi = 0; mi < 4; mi++) {
                    #pragma unroll
                    for (int p = 0; p < 2; p++) {
                        mma16816(c[mi][2 * p],     a[mi], b[p][0], b[p][1]);
                        mma16816(c[mi][2 * p + 1], a[mi], b[p][2], b[p][3]);
                    }
                }
            }
        }

        if (s + 1 < NSTEP) {
            __half* bd = Bs + (size_t)nbuf * BUF_HALFS + ldrow * LDS + ldc * 8;
            #pragma unroll
            for (int i = 0; i < 4; i++) {
                __half2 s2 = __half2half2(bscl[i]);
                uint32_t v[4];
                v[0] = dq2((uint32_t)breg[i].x, s2);
                v[1] = dq2((uint32_t)breg[i].y, s2);
                v[2] = dq2((uint32_t)breg[i].z, s2);
                v[3] = dq2((uint32_t)breg[i].w, s2);
                *reinterpret_cast<uint4*>(bd + (size_t)i * 32 * LDS) =
                    *reinterpret_cast<uint4*>(v);
            }
            asm volatile("cp.async.wait_group 0;\n" ::: "memory");
        }
        __syncthreads();
    }

    // ------------------------------ epilogue ------------------------------
    const int is32 = g_is32;
    #pragma unroll
    for (int mi = 0; mi < 4; mi++) {
        const int r0 = m0 + wm * 64 + mi * 16 + (lane >> 2);
        #pragma unroll
        for (int ni = 0; ni < 4; ni++) {
            const int col = n0 + wn * 32 + ni * 8 + (lane & 3) * 2;
            // emulate the reference's fp16 rounding of the output
            __half h00 = __float2half_rn(c[mi][ni][0]);
            __half h01 = __float2half_rn(c[mi][ni][1]);
            __half h10 = __float2half_rn(c[mi][ni][2]);
            __half h11 = __float2half_rn(c[mi][ni][3]);
            if (is32) {
                float* O = (float*)Ov;
                float2 v0 = make_float2(__half2float(h00), __half2float(h01));
                float2 v1 = make_float2(__half2float(h10), __half2float(h11));
                *reinterpret_cast<float2*>(O + (size_t)r0 * Ndim + col) = v0;
                *reinterpret_cast<float2*>(O + (size_t)(r0 + 8) * Ndim + col) = v1;
            } else {
                __half* O = (__half*)Ov;
                *reinterpret_cast<__half2*>(O + (size_t)r0 * Ndim + col) =
                    __halves2half2(h00, h01);
                *reinterpret_cast<__half2*>(O + (size_t)(r0 + 8) * Ndim + col) =
                    __halves2half2(h10, h11);
            }
        }
    }
}

// ------------------------------ launcher -----------------------------------
extern "C" void kernel_launch(void* const* d_in, const int* in_sizes, int n_in,
                              void* d_out, int out_size) {
    (void)out_size;
    const void* X = nullptr;
    const void* W = nullptr;
    const void* S = nullptr;
    for (int i = 0; i < n_in; i++) {
        long long sz = in_sizes[i];
        if (sz == XN) X = d_in[i];
        else if (sz == WN) W = d_in[i];
        else if (sz == SN) S = d_in[i];
    }
    if (!X || !W || !S) return;

    sniff_kernel<<<1, 32>>>(X);

    {
        int t = 256;
        long long bx = (XN + t - 1) / t;
        cvt_x_kernel<<<(unsigned)bx, t>>>(X);
        long long bs = (SN + t - 1) / t;
        cvt_s_kernel<<<(unsigned)bs, t>>>(S);
    }

    cudaFuncSetAttribute(w4a16_gemm, cudaFuncAttributeMaxDynamicSharedMemorySize,
                         SMEM_BYTES);
    const int grid = (Mdim / BM) * (Ndim / BN);  // 5504
    w4a16_gemm<<<grid, THREADS, SMEM_BYTES>>>((const int*)W, d_out);
}